// round 4
// baseline (speedup 1.0000x reference)
#include <cuda_runtime.h>
#include <math.h>

// Problem constants
#define BN    8192
#define NINPC 256
#define NHIDC 1024
#define NBO   8
#define BSO   128

// ---------------------------------------------------------------------------
// Scratch (device globals — no allocation allowed in kernel_launch)
// ---------------------------------------------------------------------------
__device__ float g_kk  [BN * 64];        // x @ Wk1[1]
__device__ float g_v1  [BN * 512];       // x @ Wv1[1]
__device__ float g_q   [BN * 512];       // hq @ Wq1  (b, k*64+n)
__device__ float g_s   [BN * 8];         // sigmoid(l1)
__device__ float g_mask[BN * 8];         // top-k mask per block
__device__ float g_gx  [BN * 8 * 384];   // GRU input gates
__device__ float g_gh  [BN * 8 * 384];   // GRU hidden gates
__device__ float g_hn  [BN * 1024];      // hx_new (pre-att)
__device__ float g_q2  [BN * 512];
__device__ float g_k2  [BN * 512];
__device__ float g_v2  [BN * 512];
__device__ float g_o   [BN * 512];       // attention-2 output

// ---------------------------------------------------------------------------
// Generic 64x64 fp32 tiled GEMM, BK=16, 256 threads, 4x4 micro-tile.
// Batched over blockIdx.z:
//   A element  = A[z*aZoff  + row*lda + k]   (block-diagonal column slice)
//   B element  = B[z*bZstr  + k*ldb  + n]
//   C element  = C[z*cZoff  + row*ldc + n]
// mode 0: C = acc
// mode 1: C = sv[row*8+z]*acc + bias[z*biasStride+n]   (gx epilogue)
// mode 2: C = acc + bias[z*biasStride+n]               (gh epilogue)
// All dims assumed: M%64==0, N%64==0, K%16==0 (true for every call here).
// ---------------------------------------------------------------------------
__global__ void gemm_tile(const float* __restrict__ A, int lda, int aZoff,
                          const float* __restrict__ Bm, int ldb, long bZstr,
                          float* __restrict__ C, int ldc, int cZoff,
                          int K, int mode,
                          const float* __restrict__ sv,
                          const float* __restrict__ bias, int biasStride)
{
    __shared__ float As[16][68];   // transposed A tile, padded
    __shared__ float Bs[16][64];

    const int z = blockIdx.z;
    const float* Az = A + (long)z * aZoff;
    const float* Bz = Bm + (long)z * bZstr;
    float*       Cz = C + (long)z * cZoff;

    const int m0 = blockIdx.y * 64;
    const int n0 = blockIdx.x * 64;
    const int tid = threadIdx.x;
    const int tx = tid & 15, ty = tid >> 4;
    const int arow = tid >> 2, ak = (tid & 3) << 2;
    const int bk = tid >> 4,  bn = (tid & 15) << 2;

    float acc[4][4] = {};

    for (int k0 = 0; k0 < K; k0 += 16) {
        float4 a4 = *(const float4*)(Az + (long)(m0 + arow) * lda + k0 + ak);
        float4 b4 = *(const float4*)(Bz + (long)(k0 + bk) * ldb + n0 + bn);
        __syncthreads();
        As[ak + 0][arow] = a4.x;
        As[ak + 1][arow] = a4.y;
        As[ak + 2][arow] = a4.z;
        As[ak + 3][arow] = a4.w;
        *(float4*)&Bs[bk][bn] = b4;
        __syncthreads();
#pragma unroll
        for (int kk = 0; kk < 16; kk++) {
            float4 av = *(const float4*)&As[kk][ty * 4];
            float4 bv = *(const float4*)&Bs[kk][tx * 4];
            float a_[4] = {av.x, av.y, av.z, av.w};
            float b_[4] = {bv.x, bv.y, bv.z, bv.w};
#pragma unroll
            for (int i = 0; i < 4; i++)
#pragma unroll
                for (int j = 0; j < 4; j++)
                    acc[i][j] += a_[i] * b_[j];
        }
    }

#pragma unroll
    for (int i = 0; i < 4; i++) {
        const int r = m0 + ty * 4 + i;
        float vals[4];
#pragma unroll
        for (int j = 0; j < 4; j++) {
            float v = acc[i][j];
            const int n = n0 + tx * 4 + j;
            if (mode == 1)      v = sv[(long)r * 8 + z] * v + bias[z * biasStride + n];
            else if (mode == 2) v = v + bias[z * biasStride + n];
            vals[j] = v;
        }
        float4 o4 = make_float4(vals[0], vals[1], vals[2], vals[3]);
        *(float4*)(Cz + (long)r * ldc + n0 + tx * 4) = o4;
    }
}

// ---------------------------------------------------------------------------
// l1 score, sigmoid, and top-k mask.  One thread per (b,k); 8 threads per b
// aligned within a warp so the 8 scores can be exchanged via shuffle.
// Reference: top_k on null_score p0 = sigmoid(-l1) picks 4 LARGEST p0 (ties ->
// lower index) and masks them 0.  Equivalent rank rule on l1:
//   rank_k = #{ j : l1[j] < l1[k]  ||  (l1[j]==l1[k] && j<k) },  mask = rank>=4
// ---------------------------------------------------------------------------
__global__ void score_mask_kernel()
{
    const int idx = blockIdx.x * blockDim.x + threadIdx.x;   // 0 .. BN*8-1
    const int b = idx >> 3, k = idx & 7;
    const float* q  = g_q  + (long)b * 512 + k * 64;
    const float* kk = g_kk + (long)b * 64;
    float l = 0.f;
#pragma unroll
    for (int d = 0; d < 64; d++) l += q[d] * kk[d];
    l *= 0.125f;

    const int base = (threadIdx.x & 31) & ~7;
    int cnt = 0;
#pragma unroll
    for (int j = 0; j < 8; j++) {
        float lj = __shfl_sync(0xFFFFFFFFu, l, base + j);
        if (lj < l || (lj == l && j < k)) cnt++;
    }
    g_mask[idx] = (cnt < 4) ? 0.f : 1.f;
    g_s[idx]    = 1.f / (1.f + expf(-l));
}

// ---------------------------------------------------------------------------
// GRU elementwise: hx_new = (1-z)*n + z*h
// ---------------------------------------------------------------------------
__global__ void gru_kernel(const float* __restrict__ hx)
{
    const long idx = (long)blockIdx.x * blockDim.x + threadIdx.x; // BN*1024
    const int  e   = (int)(idx & 127);
    const long bk  = idx >> 7;                                    // b*8+k
    const float* gx = g_gx + bk * 384;
    const float* gh = g_gh + bk * 384;
    const float xr = gx[e], xz = gx[e + 128], xn = gx[e + 256];
    const float hr = gh[e], hz = gh[e + 128], hn = gh[e + 256];
    const float h  = hx[idx];
    const float r  = 1.f / (1.f + expf(-(xr + hr)));
    const float zz = 1.f / (1.f + expf(-(xz + hz)));
    const float n  = tanhf(xn + r * hn);
    g_hn[idx] = (1.f - zz) * n + zz * h;
}

// ---------------------------------------------------------------------------
// Second attention: per b, 4 heads x 8 query-blocks x 8 key-blocks, dim 16.
// One warp per b; one lane per (q-block, head).
// ---------------------------------------------------------------------------
__global__ void attn2_kernel()
{
    const int gwarp = (blockIdx.x * blockDim.x + threadIdx.x) >> 5; // = b
    const int lane  = threadIdx.x & 31;
    const int qb = lane >> 2, h = lane & 3;
    const long boff = (long)gwarp * 512;

    float qv[16];
    const float* qp = g_q2 + boff + qb * 64 + h * 16;
#pragma unroll
    for (int i = 0; i < 16; i++) qv[i] = qp[i];

    float sc[8];
#pragma unroll
    for (int kb = 0; kb < 8; kb++) {
        const float* kp = g_k2 + boff + kb * 64 + h * 16;
        float d = 0.f;
#pragma unroll
        for (int i = 0; i < 16; i++) d += qv[i] * kp[i];
        sc[kb] = d * 0.25f;
    }
    float mx = sc[0];
#pragma unroll
    for (int kb = 1; kb < 8; kb++) mx = fmaxf(mx, sc[kb]);
    float den = 0.f;
#pragma unroll
    for (int kb = 0; kb < 8; kb++) { sc[kb] = expf(sc[kb] - mx); den += sc[kb]; }
    const float inv = 1.f / den;

    float o[16] = {};
#pragma unroll
    for (int kb = 0; kb < 8; kb++) {
        const float* vp = g_v2 + boff + kb * 64 + h * 16;
        const float w = sc[kb] * inv;
#pragma unroll
        for (int i = 0; i < 16; i++) o[i] += w * vp[i];
    }
    float* op = g_o + boff + qb * 64 + h * 16;
#pragma unroll
    for (int i = 0; i < 16; i++) op[i] = o[i];
}

// ---------------------------------------------------------------------------
// Final: dual GEMM o@(gate_w|fc_w), gated att, add to hx_new, masked blend,
// and write BOTH outputs.  M = BN*8 = 65536, K = 64, N = 128.
// ---------------------------------------------------------------------------
__global__ void final_kernel(const float* __restrict__ gw, const float* __restrict__ gb,
                             const float* __restrict__ fw, const float* __restrict__ fb,
                             const float* __restrict__ hx,
                             float* __restrict__ outHx, float* __restrict__ outMask)
{
    __shared__ float As[16][68];
    __shared__ float Gs[16][64];
    __shared__ float Fs[16][64];

    const int m0 = blockIdx.y * 64;
    const int n0 = blockIdx.x * 64;
    const int tid = threadIdx.x;
    const int tx = tid & 15, ty = tid >> 4;
    const int arow = tid >> 2, ak = (tid & 3) << 2;
    const int bk = tid >> 4,  bn = (tid & 15) << 2;

    float accG[4][4] = {}, accF[4][4] = {};

    for (int k0 = 0; k0 < 64; k0 += 16) {
        float4 a4 = *(const float4*)(g_o + (long)(m0 + arow) * 64 + k0 + ak);
        float4 g4 = *(const float4*)(gw + (long)(k0 + bk) * 128 + n0 + bn);
        float4 f4 = *(const float4*)(fw + (long)(k0 + bk) * 128 + n0 + bn);
        __syncthreads();
        As[ak + 0][arow] = a4.x;
        As[ak + 1][arow] = a4.y;
        As[ak + 2][arow] = a4.z;
        As[ak + 3][arow] = a4.w;
        *(float4*)&Gs[bk][bn] = g4;
        *(float4*)&Fs[bk][bn] = f4;
        __syncthreads();
#pragma unroll
        for (int kk = 0; kk < 16; kk++) {
            float4 av = *(const float4*)&As[kk][ty * 4];
            float4 gv = *(const float4*)&Gs[kk][tx * 4];
            float4 fv = *(const float4*)&Fs[kk][tx * 4];
            float a_[4] = {av.x, av.y, av.z, av.w};
            float g_[4] = {gv.x, gv.y, gv.z, gv.w};
            float f_[4] = {fv.x, fv.y, fv.z, fv.w};
#pragma unroll
            for (int i = 0; i < 4; i++)
#pragma unroll
                for (int j = 0; j < 4; j++) {
                    accG[i][j] += a_[i] * g_[j];
                    accF[i][j] += a_[i] * f_[j];
                }
        }
    }

#pragma unroll
    for (int i = 0; i < 4; i++) {
        const int r = m0 + ty * 4 + i;            // = b*8 + k
        const float m = g_mask[r];
        const long base = (long)r * 128 + n0 + tx * 4;
        float hv[4], mv[4];
#pragma unroll
        for (int j = 0; j < 4; j++) {
            const int n = n0 + tx * 4 + j;
            const float u = 1.f / (1.f + expf(-(accG[i][j] + gb[n])));
            const float t = tanhf(accF[i][j] + fb[n]);
            const float h2 = g_hn[base + j] + u * t;
            hv[j] = m * h2 + (1.f - m) * hx[base + j];
            mv[j] = m;
        }
        *(float4*)(outHx + base)   = make_float4(hv[0], hv[1], hv[2], hv[3]);
        *(float4*)(outMask + base) = make_float4(mv[0], mv[1], mv[2], mv[3]);
    }
}

// ---------------------------------------------------------------------------
// Host launcher — graph-capturable (kernel launches only)
// ---------------------------------------------------------------------------
extern "C" void kernel_launch(void* const* d_in, const int* in_sizes, int n_in,
                              void* d_out, int out_size)
{
    const float* inp    = (const float*)d_in[0];
    const float* hx     = (const float*)d_in[1];
    /* d_in[2] = step (unused) */
    const float* Wq1    = (const float*)d_in[3];
    const float* Wk1    = (const float*)d_in[4];
    const float* Wv1    = (const float*)d_in[5];
    const float* Wq2    = (const float*)d_in[6];
    const float* Wk2    = (const float*)d_in[7];
    const float* Wv2    = (const float*)d_in[8];
    const float* fc_w   = (const float*)d_in[9];
    const float* fc_b   = (const float*)d_in[10];
    const float* gate_w = (const float*)d_in[11];
    const float* gate_b = (const float*)d_in[12];
    const float* gru_wi = (const float*)d_in[13];
    const float* gru_wh = (const float*)d_in[14];
    const float* gru_bi = (const float*)d_in[15];
    const float* gru_bh = (const float*)d_in[16];

    float* outHx   = (float*)d_out;
    float* outMask = outHx + (long)BN * NHIDC;

    float *pkk, *pv1, *pq, *ps, *pgx, *pgh, *phn, *pq2, *pk2, *pv2;
    cudaGetSymbolAddress((void**)&pkk, g_kk);
    cudaGetSymbolAddress((void**)&pv1, g_v1);
    cudaGetSymbolAddress((void**)&pq,  g_q);
    cudaGetSymbolAddress((void**)&ps,  g_s);
    cudaGetSymbolAddress((void**)&pgx, g_gx);
    cudaGetSymbolAddress((void**)&pgh, g_gh);
    cudaGetSymbolAddress((void**)&phn, g_hn);
    cudaGetSymbolAddress((void**)&pq2, g_q2);
    cudaGetSymbolAddress((void**)&pk2, g_k2);
    cudaGetSymbolAddress((void**)&pv2, g_v2);

    // kk = x @ Wk1[1]            (8192,256)x(256,64)
    gemm_tile<<<dim3(1, BN / 64, 1), 256>>>(inp, NINPC, 0,
                                            Wk1 + 256 * 64, 64, 0,
                                            pkk, 64, 0, 256, 0, nullptr, nullptr, 0);
    // v1 = x @ Wv1[1]            (8192,256)x(256,512)
    gemm_tile<<<dim3(8, BN / 64, 1), 256>>>(inp, NINPC, 0,
                                            Wv1 + 256 * 512, 512, 0,
                                            pv1, 512, 0, 256, 0, nullptr, nullptr, 0);
    // q[k] = hq[k] @ Wq1[k]      batched z=8: (8192,128)x(128,64)
    gemm_tile<<<dim3(1, BN / 64, 8), 256>>>(hx, NHIDC, 128,
                                            Wq1, 64, 128 * 64,
                                            pq, 512, 64, 128, 0, nullptr, nullptr, 0);
    // l1, sigmoid, top-k mask
    score_mask_kernel<<<BN * 8 / 256, 256>>>();
    // gx[k] = s*(v1 @ gru_wi[k]) + bi[k]   batched z=8: (8192,512)x(512,384)
    gemm_tile<<<dim3(6, BN / 64, 8), 256>>>(pv1, 512, 0,
                                            gru_wi, 384, 512L * 384,
                                            pgx, 3072, 384, 512, 1, ps, gru_bi, 384);
    // gh[k] = hq[k] @ gru_wh[k] + bh[k]    batched z=8: (8192,128)x(128,384)
    gemm_tile<<<dim3(6, BN / 64, 8), 256>>>(hx, NHIDC, 128,
                                            gru_wh, 384, 128L * 384,
                                            pgh, 3072, 384, 128, 2, nullptr, gru_bh, 384);
    // GRU elementwise -> hx_new
    gru_kernel<<<BN * NHIDC / 256, 256>>>(hx);
    // q2/k2/v2 = hx_new[k] @ W*2[k]        batched z=8: (8192,128)x(128,64)
    gemm_tile<<<dim3(1, BN / 64, 8), 256>>>(phn, NHIDC, 128, Wq2, 64, 128 * 64,
                                            pq2, 512, 64, 128, 0, nullptr, nullptr, 0);
    gemm_tile<<<dim3(1, BN / 64, 8), 256>>>(phn, NHIDC, 128, Wk2, 64, 128 * 64,
                                            pk2, 512, 64, 128, 0, nullptr, nullptr, 0);
    gemm_tile<<<dim3(1, BN / 64, 8), 256>>>(phn, NHIDC, 128, Wv2, 64, 128 * 64,
                                            pv2, 512, 64, 128, 0, nullptr, nullptr, 0);
    // second attention -> o
    attn2_kernel<<<BN * 32 / 256, 256>>>();
    // dual GEMM + gating + masked blend + both outputs
    final_kernel<<<dim3(2, BN * 8 / 64), 256>>>(gate_w, gate_b, fc_w, fc_b,
                                                hx, outHx, outMask);
    (void)in_sizes; (void)n_in; (void)out_size;
}

// round 5
// speedup vs baseline: 1.0003x; 1.0003x over previous
#include <cuda_runtime.h>
#include <math.h>

// Problem constants
#define BN    8192
#define NINPC 256
#define NHIDC 1024
#define NBO   8
#define BSO   128

// ---------------------------------------------------------------------------
// Scratch (device globals — no allocation allowed in kernel_launch)
// ---------------------------------------------------------------------------
__device__ float g_kk  [BN * 64];        // x @ Wk1[1]
__device__ float g_v1  [BN * 512];       // x @ Wv1[1]
__device__ float g_q   [BN * 512];       // hq @ Wq1  (b, k*64+n)
__device__ float g_s   [BN * 8];         // sigmoid(l1)
__device__ float g_mask[BN * 8];         // top-k mask per block
__device__ float g_gx  [BN * 8 * 384];   // GRU input gates
__device__ float g_gh  [BN * 8 * 384];   // GRU hidden gates
__device__ float g_hn  [BN * 1024];      // hx_new (pre-att)
__device__ float g_q2  [BN * 512];
__device__ float g_k2  [BN * 512];
__device__ float g_v2  [BN * 512];
__device__ float g_o   [BN * 512];       // attention-2 output

// ---------------------------------------------------------------------------
// Generic 64x64 fp32 tiled GEMM, BK=16, 256 threads, 4x4 micro-tile.
// Batched over blockIdx.z:
//   A element  = A[z*aZoff  + row*lda + k]   (block-diagonal column slice)
//   B element  = B[z*bZstr  + k*ldb  + n]
//   C element  = C[z*cZoff  + row*ldc + n]
// mode 0: C = acc
// mode 1: C = sv[row*8+z]*acc + bias[z*biasStride+n]   (gx epilogue)
// mode 2: C = acc + bias[z*biasStride+n]               (gh epilogue)
// All dims assumed: M%64==0, N%64==0, K%16==0 (true for every call here).
// ---------------------------------------------------------------------------
__global__ void gemm_tile(const float* __restrict__ A, int lda, int aZoff,
                          const float* __restrict__ Bm, int ldb, long bZstr,
                          float* __restrict__ C, int ldc, int cZoff,
                          int K, int mode,
                          const float* __restrict__ sv,
                          const float* __restrict__ bias, int biasStride)
{
    __shared__ float As[16][68];   // transposed A tile, padded
    __shared__ float Bs[16][64];

    const int z = blockIdx.z;
    const float* Az = A + (long)z * aZoff;
    const float* Bz = Bm + (long)z * bZstr;
    float*       Cz = C + (long)z * cZoff;

    const int m0 = blockIdx.y * 64;
    const int n0 = blockIdx.x * 64;
    const int tid = threadIdx.x;
    const int tx = tid & 15, ty = tid >> 4;
    const int arow = tid >> 2, ak = (tid & 3) << 2;
    const int bk = tid >> 4,  bn = (tid & 15) << 2;

    float acc[4][4] = {};

    for (int k0 = 0; k0 < K; k0 += 16) {
        float4 a4 = *(const float4*)(Az + (long)(m0 + arow) * lda + k0 + ak);
        float4 b4 = *(const float4*)(Bz + (long)(k0 + bk) * ldb + n0 + bn);
        __syncthreads();
        As[ak + 0][arow] = a4.x;
        As[ak + 1][arow] = a4.y;
        As[ak + 2][arow] = a4.z;
        As[ak + 3][arow] = a4.w;
        *(float4*)&Bs[bk][bn] = b4;
        __syncthreads();
#pragma unroll
        for (int kk = 0; kk < 16; kk++) {
            float4 av = *(const float4*)&As[kk][ty * 4];
            float4 bv = *(const float4*)&Bs[kk][tx * 4];
            float a_[4] = {av.x, av.y, av.z, av.w};
            float b_[4] = {bv.x, bv.y, bv.z, bv.w};
#pragma unroll
            for (int i = 0; i < 4; i++)
#pragma unroll
                for (int j = 0; j < 4; j++)
                    acc[i][j] += a_[i] * b_[j];
        }
    }

#pragma unroll
    for (int i = 0; i < 4; i++) {
        const int r = m0 + ty * 4 + i;
        float vals[4];
#pragma unroll
        for (int j = 0; j < 4; j++) {
            float v = acc[i][j];
            const int n = n0 + tx * 4 + j;
            if (mode == 1)      v = sv[(long)r * 8 + z] * v + bias[z * biasStride + n];
            else if (mode == 2) v = v + bias[z * biasStride + n];
            vals[j] = v;
        }
        float4 o4 = make_float4(vals[0], vals[1], vals[2], vals[3]);
        *(float4*)(Cz + (long)r * ldc + n0 + tx * 4) = o4;
    }
}

// ---------------------------------------------------------------------------
// l1 score, sigmoid, and top-k mask.  One thread per (b,k); 8 threads per b
// aligned within a warp so the 8 scores can be exchanged via shuffle.
// Reference: top_k on null_score p0 = sigmoid(-l1) picks 4 LARGEST p0 (ties ->
// lower index) and masks them 0.  Equivalent rank rule on l1:
//   rank_k = #{ j : l1[j] < l1[k]  ||  (l1[j]==l1[k] && j<k) },  mask = rank>=4
// ---------------------------------------------------------------------------
__global__ void score_mask_kernel()
{
    const int idx = blockIdx.x * blockDim.x + threadIdx.x;   // 0 .. BN*8-1
    const int b = idx >> 3, k = idx & 7;
    const float* q  = g_q  + (long)b * 512 + k * 64;
    const float* kk = g_kk + (long)b * 64;
    float l = 0.f;
#pragma unroll
    for (int d = 0; d < 64; d++) l += q[d] * kk[d];
    l *= 0.125f;

    const int base = (threadIdx.x & 31) & ~7;
    int cnt = 0;
#pragma unroll
    for (int j = 0; j < 8; j++) {
        float lj = __shfl_sync(0xFFFFFFFFu, l, base + j);
        if (lj < l || (lj == l && j < k)) cnt++;
    }
    g_mask[idx] = (cnt < 4) ? 0.f : 1.f;
    g_s[idx]    = 1.f / (1.f + expf(-l));
}

// ---------------------------------------------------------------------------
// GRU elementwise: hx_new = (1-z)*n + z*h
// ---------------------------------------------------------------------------
__global__ void gru_kernel(const float* __restrict__ hx)
{
    const long idx = (long)blockIdx.x * blockDim.x + threadIdx.x; // BN*1024
    const int  e   = (int)(idx & 127);
    const long bk  = idx >> 7;                                    // b*8+k
    const float* gx = g_gx + bk * 384;
    const float* gh = g_gh + bk * 384;
    const float xr = gx[e], xz = gx[e + 128], xn = gx[e + 256];
    const float hr = gh[e], hz = gh[e + 128], hn = gh[e + 256];
    const float h  = hx[idx];
    const float r  = 1.f / (1.f + expf(-(xr + hr)));
    const float zz = 1.f / (1.f + expf(-(xz + hz)));
    const float n  = tanhf(xn + r * hn);
    g_hn[idx] = (1.f - zz) * n + zz * h;
}

// ---------------------------------------------------------------------------
// Second attention: per b, 4 heads x 8 query-blocks x 8 key-blocks, dim 16.
// One warp per b; one lane per (q-block, head).
// ---------------------------------------------------------------------------
__global__ void attn2_kernel()
{
    const int gwarp = (blockIdx.x * blockDim.x + threadIdx.x) >> 5; // = b
    const int lane  = threadIdx.x & 31;
    const int qb = lane >> 2, h = lane & 3;
    const long boff = (long)gwarp * 512;

    float qv[16];
    const float* qp = g_q2 + boff + qb * 64 + h * 16;
#pragma unroll
    for (int i = 0; i < 16; i++) qv[i] = qp[i];

    float sc[8];
#pragma unroll
    for (int kb = 0; kb < 8; kb++) {
        const float* kp = g_k2 + boff + kb * 64 + h * 16;
        float d = 0.f;
#pragma unroll
        for (int i = 0; i < 16; i++) d += qv[i] * kp[i];
        sc[kb] = d * 0.25f;
    }
    float mx = sc[0];
#pragma unroll
    for (int kb = 1; kb < 8; kb++) mx = fmaxf(mx, sc[kb]);
    float den = 0.f;
#pragma unroll
    for (int kb = 0; kb < 8; kb++) { sc[kb] = expf(sc[kb] - mx); den += sc[kb]; }
    const float inv = 1.f / den;

    float o[16] = {};
#pragma unroll
    for (int kb = 0; kb < 8; kb++) {
        const float* vp = g_v2 + boff + kb * 64 + h * 16;
        const float w = sc[kb] * inv;
#pragma unroll
        for (int i = 0; i < 16; i++) o[i] += w * vp[i];
    }
    float* op = g_o + boff + qb * 64 + h * 16;
#pragma unroll
    for (int i = 0; i < 16; i++) op[i] = o[i];
}

// ---------------------------------------------------------------------------
// Final: dual GEMM o@(gate_w|fc_w), gated att, add to hx_new, masked blend,
// and write BOTH outputs.  M = BN*8 = 65536, K = 64, N = 128.
// ---------------------------------------------------------------------------
__global__ void final_kernel(const float* __restrict__ gw, const float* __restrict__ gb,
                             const float* __restrict__ fw, const float* __restrict__ fb,
                             const float* __restrict__ hx,
                             float* __restrict__ outHx, float* __restrict__ outMask)
{
    __shared__ float As[16][68];
    __shared__ float Gs[16][64];
    __shared__ float Fs[16][64];

    const int m0 = blockIdx.y * 64;
    const int n0 = blockIdx.x * 64;
    const int tid = threadIdx.x;
    const int tx = tid & 15, ty = tid >> 4;
    const int arow = tid >> 2, ak = (tid & 3) << 2;
    const int bk = tid >> 4,  bn = (tid & 15) << 2;

    float accG[4][4] = {}, accF[4][4] = {};

    for (int k0 = 0; k0 < 64; k0 += 16) {
        float4 a4 = *(const float4*)(g_o + (long)(m0 + arow) * 64 + k0 + ak);
        float4 g4 = *(const float4*)(gw + (long)(k0 + bk) * 128 + n0 + bn);
        float4 f4 = *(const float4*)(fw + (long)(k0 + bk) * 128 + n0 + bn);
        __syncthreads();
        As[ak + 0][arow] = a4.x;
        As[ak + 1][arow] = a4.y;
        As[ak + 2][arow] = a4.z;
        As[ak + 3][arow] = a4.w;
        *(float4*)&Gs[bk][bn] = g4;
        *(float4*)&Fs[bk][bn] = f4;
        __syncthreads();
#pragma unroll
        for (int kk = 0; kk < 16; kk++) {
            float4 av = *(const float4*)&As[kk][ty * 4];
            float4 gv = *(const float4*)&Gs[kk][tx * 4];
            float4 fv = *(const float4*)&Fs[kk][tx * 4];
            float a_[4] = {av.x, av.y, av.z, av.w};
            float g_[4] = {gv.x, gv.y, gv.z, gv.w};
            float f_[4] = {fv.x, fv.y, fv.z, fv.w};
#pragma unroll
            for (int i = 0; i < 4; i++)
#pragma unroll
                for (int j = 0; j < 4; j++) {
                    accG[i][j] += a_[i] * g_[j];
                    accF[i][j] += a_[i] * f_[j];
                }
        }
    }

#pragma unroll
    for (int i = 0; i < 4; i++) {
        const int r = m0 + ty * 4 + i;            // = b*8 + k
        const float m = g_mask[r];
        const long base = (long)r * 128 + n0 + tx * 4;
        float hv[4], mv[4];
#pragma unroll
        for (int j = 0; j < 4; j++) {
            const int n = n0 + tx * 4 + j;
            const float u = 1.f / (1.f + expf(-(accG[i][j] + gb[n])));
            const float t = tanhf(accF[i][j] + fb[n]);
            const float h2 = g_hn[base + j] + u * t;
            hv[j] = m * h2 + (1.f - m) * hx[base + j];
            mv[j] = m;
        }
        *(float4*)(outHx + base)   = make_float4(hv[0], hv[1], hv[2], hv[3]);
        *(float4*)(outMask + base) = make_float4(mv[0], mv[1], mv[2], mv[3]);
    }
}

// ---------------------------------------------------------------------------
// Host launcher — graph-capturable (kernel launches only)
// ---------------------------------------------------------------------------
extern "C" void kernel_launch(void* const* d_in, const int* in_sizes, int n_in,
                              void* d_out, int out_size)
{
    const float* inp    = (const float*)d_in[0];
    const float* hx     = (const float*)d_in[1];
    /* d_in[2] = step (unused) */
    const float* Wq1    = (const float*)d_in[3];
    const float* Wk1    = (const float*)d_in[4];
    const float* Wv1    = (const float*)d_in[5];
    const float* Wq2    = (const float*)d_in[6];
    const float* Wk2    = (const float*)d_in[7];
    const float* Wv2    = (const float*)d_in[8];
    const float* fc_w   = (const float*)d_in[9];
    const float* fc_b   = (const float*)d_in[10];
    const float* gate_w = (const float*)d_in[11];
    const float* gate_b = (const float*)d_in[12];
    const float* gru_wi = (const float*)d_in[13];
    const float* gru_wh = (const float*)d_in[14];
    const float* gru_bi = (const float*)d_in[15];
    const float* gru_bh = (const float*)d_in[16];

    float* outHx   = (float*)d_out;
    float* outMask = outHx + (long)BN * NHIDC;

    float *pkk, *pv1, *pq, *ps, *pgx, *pgh, *phn, *pq2, *pk2, *pv2;
    cudaGetSymbolAddress((void**)&pkk, g_kk);
    cudaGetSymbolAddress((void**)&pv1, g_v1);
    cudaGetSymbolAddress((void**)&pq,  g_q);
    cudaGetSymbolAddress((void**)&ps,  g_s);
    cudaGetSymbolAddress((void**)&pgx, g_gx);
    cudaGetSymbolAddress((void**)&pgh, g_gh);
    cudaGetSymbolAddress((void**)&phn, g_hn);
    cudaGetSymbolAddress((void**)&pq2, g_q2);
    cudaGetSymbolAddress((void**)&pk2, g_k2);
    cudaGetSymbolAddress((void**)&pv2, g_v2);

    // kk = x @ Wk1[1]            (8192,256)x(256,64)
    gemm_tile<<<dim3(1, BN / 64, 1), 256>>>(inp, NINPC, 0,
                                            Wk1 + 256 * 64, 64, 0,
                                            pkk, 64, 0, 256, 0, nullptr, nullptr, 0);
    // v1 = x @ Wv1[1]            (8192,256)x(256,512)
    gemm_tile<<<dim3(8, BN / 64, 1), 256>>>(inp, NINPC, 0,
                                            Wv1 + 256 * 512, 512, 0,
                                            pv1, 512, 0, 256, 0, nullptr, nullptr, 0);
    // q[k] = hq[k] @ Wq1[k]      batched z=8: (8192,128)x(128,64)
    gemm_tile<<<dim3(1, BN / 64, 8), 256>>>(hx, NHIDC, 128,
                                            Wq1, 64, 128 * 64,
                                            pq, 512, 64, 128, 0, nullptr, nullptr, 0);
    // l1, sigmoid, top-k mask
    score_mask_kernel<<<BN * 8 / 256, 256>>>();
    // gx[k] = s*(v1 @ gru_wi[k]) + bi[k]   batched z=8: (8192,512)x(512,384)
    gemm_tile<<<dim3(6, BN / 64, 8), 256>>>(pv1, 512, 0,
                                            gru_wi, 384, 512L * 384,
                                            pgx, 3072, 384, 512, 1, ps, gru_bi, 384);
    // gh[k] = hq[k] @ gru_wh[k] + bh[k]    batched z=8: (8192,128)x(128,384)
    gemm_tile<<<dim3(6, BN / 64, 8), 256>>>(hx, NHIDC, 128,
                                            gru_wh, 384, 128L * 384,
                                            pgh, 3072, 384, 128, 2, nullptr, gru_bh, 384);
    // GRU elementwise -> hx_new
    gru_kernel<<<BN * NHIDC / 256, 256>>>(hx);
    // q2/k2/v2 = hx_new[k] @ W*2[k]        batched z=8: (8192,128)x(128,64)
    gemm_tile<<<dim3(1, BN / 64, 8), 256>>>(phn, NHIDC, 128, Wq2, 64, 128 * 64,
                                            pq2, 512, 64, 128, 0, nullptr, nullptr, 0);
    gemm_tile<<<dim3(1, BN / 64, 8), 256>>>(phn, NHIDC, 128, Wk2, 64, 128 * 64,
                                            pk2, 512, 64, 128, 0, nullptr, nullptr, 0);
    gemm_tile<<<dim3(1, BN / 64, 8), 256>>>(phn, NHIDC, 128, Wv2, 64, 128 * 64,
                                            pv2, 512, 64, 128, 0, nullptr, nullptr, 0);
    // second attention -> o
    attn2_kernel<<<BN * 32 / 256, 256>>>();
    // dual GEMM + gating + masked blend + both outputs
    final_kernel<<<dim3(2, BN * 8 / 64), 256>>>(gate_w, gate_b, fc_w, fc_b,
                                                hx, outHx, outMask);
    (void)in_sizes; (void)n_in; (void)out_size;
}

// round 6
// speedup vs baseline: 1.0009x; 1.0006x over previous
#include <cuda_runtime.h>
#include <math.h>

// Problem constants
#define BN    8192
#define NINPC 256
#define NHIDC 1024
#define NBO   8
#define BSO   128

// ---------------------------------------------------------------------------
// Scratch (device globals — no allocation allowed in kernel_launch)
// ---------------------------------------------------------------------------
__device__ float g_kk  [BN * 64];        // x @ Wk1[1]
__device__ float g_v1  [BN * 512];       // x @ Wv1[1]
__device__ float g_q   [BN * 512];       // hq @ Wq1  (b, k*64+n)
__device__ float g_s   [BN * 8];         // sigmoid(l1)
__device__ float g_mask[BN * 8];         // top-k mask per block
__device__ float g_gx  [BN * 8 * 384];   // GRU input gates
__device__ float g_gh  [BN * 8 * 384];   // GRU hidden gates
__device__ float g_hn  [BN * 1024];      // hx_new (pre-att)
__device__ float g_q2  [BN * 512];
__device__ float g_k2  [BN * 512];
__device__ float g_v2  [BN * 512];
__device__ float g_o   [BN * 512];       // attention-2 output

// ---------------------------------------------------------------------------
// Generic 64x64 fp32 tiled GEMM, BK=16, 256 threads, 4x4 micro-tile.
// Batched over blockIdx.z:
//   A element  = A[z*aZoff  + row*lda + k]   (block-diagonal column slice)
//   B element  = B[z*bZstr  + k*ldb  + n]
//   C element  = C[z*cZoff  + row*ldc + n]
// mode 0: C = acc
// mode 1: C = sv[row*8+z]*acc + bias[z*biasStride+n]   (gx epilogue)
// mode 2: C = acc + bias[z*biasStride+n]               (gh epilogue)
// All dims assumed: M%64==0, N%64==0, K%16==0 (true for every call here).
// ---------------------------------------------------------------------------
__global__ void gemm_tile(const float* __restrict__ A, int lda, int aZoff,
                          const float* __restrict__ Bm, int ldb, long bZstr,
                          float* __restrict__ C, int ldc, int cZoff,
                          int K, int mode,
                          const float* __restrict__ sv,
                          const float* __restrict__ bias, int biasStride)
{
    __shared__ float As[16][68];   // transposed A tile, padded
    __shared__ float Bs[16][64];

    const int z = blockIdx.z;
    const float* Az = A + (long)z * aZoff;
    const float* Bz = Bm + (long)z * bZstr;
    float*       Cz = C + (long)z * cZoff;

    const int m0 = blockIdx.y * 64;
    const int n0 = blockIdx.x * 64;
    const int tid = threadIdx.x;
    const int tx = tid & 15, ty = tid >> 4;
    const int arow = tid >> 2, ak = (tid & 3) << 2;
    const int bk = tid >> 4,  bn = (tid & 15) << 2;

    float acc[4][4] = {};

    for (int k0 = 0; k0 < K; k0 += 16) {
        float4 a4 = *(const float4*)(Az + (long)(m0 + arow) * lda + k0 + ak);
        float4 b4 = *(const float4*)(Bz + (long)(k0 + bk) * ldb + n0 + bn);
        __syncthreads();
        As[ak + 0][arow] = a4.x;
        As[ak + 1][arow] = a4.y;
        As[ak + 2][arow] = a4.z;
        As[ak + 3][arow] = a4.w;
        *(float4*)&Bs[bk][bn] = b4;
        __syncthreads();
#pragma unroll
        for (int kk = 0; kk < 16; kk++) {
            float4 av = *(const float4*)&As[kk][ty * 4];
            float4 bv = *(const float4*)&Bs[kk][tx * 4];
            float a_[4] = {av.x, av.y, av.z, av.w};
            float b_[4] = {bv.x, bv.y, bv.z, bv.w};
#pragma unroll
            for (int i = 0; i < 4; i++)
#pragma unroll
                for (int j = 0; j < 4; j++)
                    acc[i][j] += a_[i] * b_[j];
        }
    }

#pragma unroll
    for (int i = 0; i < 4; i++) {
        const int r = m0 + ty * 4 + i;
        float vals[4];
#pragma unroll
        for (int j = 0; j < 4; j++) {
            float v = acc[i][j];
            const int n = n0 + tx * 4 + j;
            if (mode == 1)      v = sv[(long)r * 8 + z] * v + bias[z * biasStride + n];
            else if (mode == 2) v = v + bias[z * biasStride + n];
            vals[j] = v;
        }
        float4 o4 = make_float4(vals[0], vals[1], vals[2], vals[3]);
        *(float4*)(Cz + (long)r * ldc + n0 + tx * 4) = o4;
    }
}

// ---------------------------------------------------------------------------
// l1 score, sigmoid, and top-k mask.  One thread per (b,k); 8 threads per b
// aligned within a warp so the 8 scores can be exchanged via shuffle.
// Reference: top_k on null_score p0 = sigmoid(-l1) picks 4 LARGEST p0 (ties ->
// lower index) and masks them 0.  Equivalent rank rule on l1:
//   rank_k = #{ j : l1[j] < l1[k]  ||  (l1[j]==l1[k] && j<k) },  mask = rank>=4
// ---------------------------------------------------------------------------
__global__ void score_mask_kernel()
{
    const int idx = blockIdx.x * blockDim.x + threadIdx.x;   // 0 .. BN*8-1
    const int b = idx >> 3, k = idx & 7;
    const float* q  = g_q  + (long)b * 512 + k * 64;
    const float* kk = g_kk + (long)b * 64;
    float l = 0.f;
#pragma unroll
    for (int d = 0; d < 64; d++) l += q[d] * kk[d];
    l *= 0.125f;

    const int base = (threadIdx.x & 31) & ~7;
    int cnt = 0;
#pragma unroll
    for (int j = 0; j < 8; j++) {
        float lj = __shfl_sync(0xFFFFFFFFu, l, base + j);
        if (lj < l || (lj == l && j < k)) cnt++;
    }
    g_mask[idx] = (cnt < 4) ? 0.f : 1.f;
    g_s[idx]    = 1.f / (1.f + expf(-l));
}

// ---------------------------------------------------------------------------
// GRU elementwise: hx_new = (1-z)*n + z*h
// ---------------------------------------------------------------------------
__global__ void gru_kernel(const float* __restrict__ hx)
{
    const long idx = (long)blockIdx.x * blockDim.x + threadIdx.x; // BN*1024
    const int  e   = (int)(idx & 127);
    const long bk  = idx >> 7;                                    // b*8+k
    const float* gx = g_gx + bk * 384;
    const float* gh = g_gh + bk * 384;
    const float xr = gx[e], xz = gx[e + 128], xn = gx[e + 256];
    const float hr = gh[e], hz = gh[e + 128], hn = gh[e + 256];
    const float h  = hx[idx];
    const float r  = 1.f / (1.f + expf(-(xr + hr)));
    const float zz = 1.f / (1.f + expf(-(xz + hz)));
    const float n  = tanhf(xn + r * hn);
    g_hn[idx] = (1.f - zz) * n + zz * h;
}

// ---------------------------------------------------------------------------
// Second attention: per b, 4 heads x 8 query-blocks x 8 key-blocks, dim 16.
// One warp per b; one lane per (q-block, head).
// ---------------------------------------------------------------------------
__global__ void attn2_kernel()
{
    const int gwarp = (blockIdx.x * blockDim.x + threadIdx.x) >> 5; // = b
    const int lane  = threadIdx.x & 31;
    const int qb = lane >> 2, h = lane & 3;
    const long boff = (long)gwarp * 512;

    float qv[16];
    const float* qp = g_q2 + boff + qb * 64 + h * 16;
#pragma unroll
    for (int i = 0; i < 16; i++) qv[i] = qp[i];

    float sc[8];
#pragma unroll
    for (int kb = 0; kb < 8; kb++) {
        const float* kp = g_k2 + boff + kb * 64 + h * 16;
        float d = 0.f;
#pragma unroll
        for (int i = 0; i < 16; i++) d += qv[i] * kp[i];
        sc[kb] = d * 0.25f;
    }
    float mx = sc[0];
#pragma unroll
    for (int kb = 1; kb < 8; kb++) mx = fmaxf(mx, sc[kb]);
    float den = 0.f;
#pragma unroll
    for (int kb = 0; kb < 8; kb++) { sc[kb] = expf(sc[kb] - mx); den += sc[kb]; }
    const float inv = 1.f / den;

    float o[16] = {};
#pragma unroll
    for (int kb = 0; kb < 8; kb++) {
        const float* vp = g_v2 + boff + kb * 64 + h * 16;
        const float w = sc[kb] * inv;
#pragma unroll
        for (int i = 0; i < 16; i++) o[i] += w * vp[i];
    }
    float* op = g_o + boff + qb * 64 + h * 16;
#pragma unroll
    for (int i = 0; i < 16; i++) op[i] = o[i];
}

// ---------------------------------------------------------------------------
// Final: dual GEMM o@(gate_w|fc_w), gated att, add to hx_new, masked blend,
// and write BOTH outputs.  M = BN*8 = 65536, K = 64, N = 128.
// ---------------------------------------------------------------------------
__global__ void final_kernel(const float* __restrict__ gw, const float* __restrict__ gb,
                             const float* __restrict__ fw, const float* __restrict__ fb,
                             const float* __restrict__ hx,
                             float* __restrict__ outHx, float* __restrict__ outMask)
{
    __shared__ float As[16][68];
    __shared__ float Gs[16][64];
    __shared__ float Fs[16][64];

    const int m0 = blockIdx.y * 64;
    const int n0 = blockIdx.x * 64;
    const int tid = threadIdx.x;
    const int tx = tid & 15, ty = tid >> 4;
    const int arow = tid >> 2, ak = (tid & 3) << 2;
    const int bk = tid >> 4,  bn = (tid & 15) << 2;

    float accG[4][4] = {}, accF[4][4] = {};

    for (int k0 = 0; k0 < 64; k0 += 16) {
        float4 a4 = *(const float4*)(g_o + (long)(m0 + arow) * 64 + k0 + ak);
        float4 g4 = *(const float4*)(gw + (long)(k0 + bk) * 128 + n0 + bn);
        float4 f4 = *(const float4*)(fw + (long)(k0 + bk) * 128 + n0 + bn);
        __syncthreads();
        As[ak + 0][arow] = a4.x;
        As[ak + 1][arow] = a4.y;
        As[ak + 2][arow] = a4.z;
        As[ak + 3][arow] = a4.w;
        *(float4*)&Gs[bk][bn] = g4;
        *(float4*)&Fs[bk][bn] = f4;
        __syncthreads();
#pragma unroll
        for (int kk = 0; kk < 16; kk++) {
            float4 av = *(const float4*)&As[kk][ty * 4];
            float4 gv = *(const float4*)&Gs[kk][tx * 4];
            float4 fv = *(const float4*)&Fs[kk][tx * 4];
            float a_[4] = {av.x, av.y, av.z, av.w};
            float g_[4] = {gv.x, gv.y, gv.z, gv.w};
            float f_[4] = {fv.x, fv.y, fv.z, fv.w};
#pragma unroll
            for (int i = 0; i < 4; i++)
#pragma unroll
                for (int j = 0; j < 4; j++) {
                    accG[i][j] += a_[i] * g_[j];
                    accF[i][j] += a_[i] * f_[j];
                }
        }
    }

#pragma unroll
    for (int i = 0; i < 4; i++) {
        const int r = m0 + ty * 4 + i;            // = b*8 + k
        const float m = g_mask[r];
        const long base = (long)r * 128 + n0 + tx * 4;
        float hv[4], mv[4];
#pragma unroll
        for (int j = 0; j < 4; j++) {
            const int n = n0 + tx * 4 + j;
            const float u = 1.f / (1.f + expf(-(accG[i][j] + gb[n])));
            const float t = tanhf(accF[i][j] + fb[n]);
            const float h2 = g_hn[base + j] + u * t;
            hv[j] = m * h2 + (1.f - m) * hx[base + j];
            mv[j] = m;
        }
        *(float4*)(outHx + base)   = make_float4(hv[0], hv[1], hv[2], hv[3]);
        *(float4*)(outMask + base) = make_float4(mv[0], mv[1], mv[2], mv[3]);
    }
}

// ---------------------------------------------------------------------------
// Host launcher — graph-capturable (kernel launches only)
// ---------------------------------------------------------------------------
extern "C" void kernel_launch(void* const* d_in, const int* in_sizes, int n_in,
                              void* d_out, int out_size)
{
    const float* inp    = (const float*)d_in[0];
    const float* hx     = (const float*)d_in[1];
    /* d_in[2] = step (unused) */
    const float* Wq1    = (const float*)d_in[3];
    const float* Wk1    = (const float*)d_in[4];
    const float* Wv1    = (const float*)d_in[5];
    const float* Wq2    = (const float*)d_in[6];
    const float* Wk2    = (const float*)d_in[7];
    const float* Wv2    = (const float*)d_in[8];
    const float* fc_w   = (const float*)d_in[9];
    const float* fc_b   = (const float*)d_in[10];
    const float* gate_w = (const float*)d_in[11];
    const float* gate_b = (const float*)d_in[12];
    const float* gru_wi = (const float*)d_in[13];
    const float* gru_wh = (const float*)d_in[14];
    const float* gru_bi = (const float*)d_in[15];
    const float* gru_bh = (const float*)d_in[16];

    float* outHx   = (float*)d_out;
    float* outMask = outHx + (long)BN * NHIDC;

    float *pkk, *pv1, *pq, *ps, *pgx, *pgh, *phn, *pq2, *pk2, *pv2;
    cudaGetSymbolAddress((void**)&pkk, g_kk);
    cudaGetSymbolAddress((void**)&pv1, g_v1);
    cudaGetSymbolAddress((void**)&pq,  g_q);
    cudaGetSymbolAddress((void**)&ps,  g_s);
    cudaGetSymbolAddress((void**)&pgx, g_gx);
    cudaGetSymbolAddress((void**)&pgh, g_gh);
    cudaGetSymbolAddress((void**)&phn, g_hn);
    cudaGetSymbolAddress((void**)&pq2, g_q2);
    cudaGetSymbolAddress((void**)&pk2, g_k2);
    cudaGetSymbolAddress((void**)&pv2, g_v2);

    // kk = x @ Wk1[1]            (8192,256)x(256,64)
    gemm_tile<<<dim3(1, BN / 64, 1), 256>>>(inp, NINPC, 0,
                                            Wk1 + 256 * 64, 64, 0,
                                            pkk, 64, 0, 256, 0, nullptr, nullptr, 0);
    // v1 = x @ Wv1[1]            (8192,256)x(256,512)
    gemm_tile<<<dim3(8, BN / 64, 1), 256>>>(inp, NINPC, 0,
                                            Wv1 + 256 * 512, 512, 0,
                                            pv1, 512, 0, 256, 0, nullptr, nullptr, 0);
    // q[k] = hq[k] @ Wq1[k]      batched z=8: (8192,128)x(128,64)
    gemm_tile<<<dim3(1, BN / 64, 8), 256>>>(hx, NHIDC, 128,
                                            Wq1, 64, 128 * 64,
                                            pq, 512, 64, 128, 0, nullptr, nullptr, 0);
    // l1, sigmoid, top-k mask
    score_mask_kernel<<<BN * 8 / 256, 256>>>();
    // gx[k] = s*(v1 @ gru_wi[k]) + bi[k]   batched z=8: (8192,512)x(512,384)
    gemm_tile<<<dim3(6, BN / 64, 8), 256>>>(pv1, 512, 0,
                                            gru_wi, 384, 512L * 384,
                                            pgx, 3072, 384, 512, 1, ps, gru_bi, 384);
    // gh[k] = hq[k] @ gru_wh[k] + bh[k]    batched z=8: (8192,128)x(128,384)
    gemm_tile<<<dim3(6, BN / 64, 8), 256>>>(hx, NHIDC, 128,
                                            gru_wh, 384, 128L * 384,
                                            pgh, 3072, 384, 128, 2, nullptr, gru_bh, 384);
    // GRU elementwise -> hx_new
    gru_kernel<<<BN * NHIDC / 256, 256>>>(hx);
    // q2/k2/v2 = hx_new[k] @ W*2[k]        batched z=8: (8192,128)x(128,64)
    gemm_tile<<<dim3(1, BN / 64, 8), 256>>>(phn, NHIDC, 128, Wq2, 64, 128 * 64,
                                            pq2, 512, 64, 128, 0, nullptr, nullptr, 0);
    gemm_tile<<<dim3(1, BN / 64, 8), 256>>>(phn, NHIDC, 128, Wk2, 64, 128 * 64,
                                            pk2, 512, 64, 128, 0, nullptr, nullptr, 0);
    gemm_tile<<<dim3(1, BN / 64, 8), 256>>>(phn, NHIDC, 128, Wv2, 64, 128 * 64,
                                            pv2, 512, 64, 128, 0, nullptr, nullptr, 0);
    // second attention -> o
    attn2_kernel<<<BN * 32 / 256, 256>>>();
    // dual GEMM + gating + masked blend + both outputs
    final_kernel<<<dim3(2, BN * 8 / 64), 256>>>(gate_w, gate_b, fc_w, fc_b,
                                                hx, outHx, outMask);
    (void)in_sizes; (void)n_in; (void)out_size;
}